// round 2
// baseline (speedup 1.0000x reference)
#include <cuda_runtime.h>
#include <math.h>

#define DIM 768
#define NHEAD 16
#define HD 48
#define SEQ 2048
#define ATTN_SCALE 0.14433756729740643f  // 1/sqrt(48)

#define BQ 64
#define BKV 64

// ---------------------------------------------------------------------------
// Scratch (device globals: allocation-guard-safe)
// ---------------------------------------------------------------------------
__device__ float g_q[8192 * DIM];
__device__ float g_k[8192 * DIM];
__device__ float g_v[8192 * DIM];
__device__ float g_ao[8192 * DIM];

// ---------------------------------------------------------------------------
// SGEMM: C[m][n] = sum_k A[m][k] * W[n][k] + bias[n]
// 128x128 block tile, BK=16, 256 threads, 8x8 per-thread microtile.
// ---------------------------------------------------------------------------
__global__ __launch_bounds__(256) void gemm_nt_bias(
    const float* __restrict__ A, const float* __restrict__ W,
    const float* __restrict__ bias, float* __restrict__ C,
    int M, int N, int K)
{
    __shared__ __align__(16) float As[16][132];
    __shared__ __align__(16) float Ws[16][132];

    const int tid = threadIdx.x;
    const int bm = blockIdx.y * 128;
    const int bn = blockIdx.x * 128;
    const int tx = tid & 15;
    const int ty = tid >> 4;

    float acc[8][8];
#pragma unroll
    for (int i = 0; i < 8; i++)
#pragma unroll
        for (int j = 0; j < 8; j++) acc[i][j] = 0.f;

    for (int k0 = 0; k0 < K; k0 += 16) {
#pragma unroll
        for (int it = 0; it < 2; it++) {
            int idx = tid + it * 256;
            int row = idx >> 2;
            int c4  = (idx & 3) * 4;
            float4 a = *(const float4*)(A + (size_t)(bm + row) * K + k0 + c4);
            As[c4 + 0][row] = a.x; As[c4 + 1][row] = a.y;
            As[c4 + 2][row] = a.z; As[c4 + 3][row] = a.w;
            float4 w = *(const float4*)(W + (size_t)(bn + row) * K + k0 + c4);
            Ws[c4 + 0][row] = w.x; Ws[c4 + 1][row] = w.y;
            Ws[c4 + 2][row] = w.z; Ws[c4 + 3][row] = w.w;
        }
        __syncthreads();

#pragma unroll
        for (int k = 0; k < 16; k++) {
            float a[8], b[8];
            *(float4*)(a)     = *(const float4*)&As[k][ty * 8];
            *(float4*)(a + 4) = *(const float4*)&As[k][ty * 8 + 4];
            *(float4*)(b)     = *(const float4*)&Ws[k][tx * 8];
            *(float4*)(b + 4) = *(const float4*)&Ws[k][tx * 8 + 4];
#pragma unroll
            for (int i = 0; i < 8; i++)
#pragma unroll
                for (int j = 0; j < 8; j++)
                    acc[i][j] += a[i] * b[j];
        }
        __syncthreads();
    }

#pragma unroll
    for (int i = 0; i < 8; i++) {
        int row = bm + ty * 8 + i;
#pragma unroll
        for (int j = 0; j < 8; j += 4) {
            int col = bn + tx * 8 + j;
            float4 bb = *(const float4*)(bias + col);
            float4 o;
            o.x = acc[i][j + 0] + bb.x;
            o.y = acc[i][j + 1] + bb.y;
            o.z = acc[i][j + 2] + bb.z;
            o.w = acc[i][j + 3] + bb.w;
            *(float4*)(C + (size_t)row * N + col) = o;
        }
    }
}

// ---------------------------------------------------------------------------
// Flash attention, micro-tiled. Block handles BQ=64 query rows of one (b,h),
// iterating over kv in BKV=64 tiles. 128 threads.
//
// Shared layout (floats, dynamic):
//   Qst[48][68]  d-major, scaled      ofs 0      (3264)
//   Kst[48][68]  d-major              ofs 3264   (3264)
//   Vs [64][48]  kv-major             ofs 6528   (3072)
//   Pt [64][68]  kv-major, [kv][q]    ofs 9600   (4352)
//   corr_s[64]                        ofs 13952
//   l_s  [64]                         ofs 14016
// total 14080 floats = 56320 bytes
//
// Phase A: thread (ty=t>>3 in 0..15 -> 4 q rows, tx=t&7 -> 8 kv cols):
//   s[4][8] via 3x LDS.128 + 32 FMA per d-step. Online softmax with
//   shfl_xor reduction over the 8-lane tx group. P -> Pt (float4 STS).
// Phase B: thread (qg=t>>3 -> 4 q rows, dg=t&7 -> 6 d cols):
//   o[4][6] += Pt * Vs, 4 vector LDS + 24 FMA per kv step.
// ---------------------------------------------------------------------------
__global__ __launch_bounds__(128) void flash_attn(
    const float* __restrict__ Q, const float* __restrict__ K,
    const float* __restrict__ V, float* __restrict__ O)
{
    extern __shared__ float sm[];
    float* Qst    = sm;             // [48][68]
    float* Kst    = sm + 3264;      // [48][68]
    float* Vs     = sm + 6528;      // [64][48]
    float* Pt     = sm + 9600;      // [64][68]
    float* corr_s = sm + 13952;     // [64]
    float* l_s    = sm + 14016;     // [64]

    const int t  = threadIdx.x;
    const int h  = blockIdx.y;
    const int b  = blockIdx.z;
    const int q0 = blockIdx.x * BQ;

    const int ty = t >> 3;   // 0..15 : q group (phase A) == qg (phase B)
    const int tx = t & 7;    // 0..7  : kv group (A) / d group (B)

    const float* Qb = Q + ((size_t)(b * SEQ + q0)) * DIM + h * HD;
    const float* Kb = K + (size_t)b * SEQ * DIM + h * HD;
    const float* Vb = V + (size_t)b * SEQ * DIM + h * HD;

    // Load Q tile transposed + scaled: 64 rows x 12 float4
    for (int idx = t; idx < BQ * 12; idx += 128) {
        int r  = idx / 12;
        int c4 = (idx % 12) << 2;
        float4 f = *(const float4*)(Qb + (size_t)r * DIM + c4);
        Qst[(c4 + 0) * 68 + r] = f.x * ATTN_SCALE;
        Qst[(c4 + 1) * 68 + r] = f.y * ATTN_SCALE;
        Qst[(c4 + 2) * 68 + r] = f.z * ATTN_SCALE;
        Qst[(c4 + 3) * 68 + r] = f.w * ATTN_SCALE;
    }

    float o[4][6];
#pragma unroll
    for (int j = 0; j < 4; j++)
#pragma unroll
        for (int jj = 0; jj < 6; jj++) o[j][jj] = 0.f;
    float m[4] = {-1e30f, -1e30f, -1e30f, -1e30f};
    float l[4] = {0.f, 0.f, 0.f, 0.f};

    for (int kv0 = 0; kv0 < SEQ; kv0 += BKV) {
        __syncthreads();  // previous phase B done (also covers Qst on iter 0)

        // Load K transposed, V direct: 64 rows x 12 float4 each
        for (int idx = t; idx < BKV * 12; idx += 128) {
            int r  = idx / 12;
            int c4 = (idx % 12) << 2;
            float4 kf = *(const float4*)(Kb + (size_t)(kv0 + r) * DIM + c4);
            Kst[(c4 + 0) * 68 + r] = kf.x;
            Kst[(c4 + 1) * 68 + r] = kf.y;
            Kst[(c4 + 2) * 68 + r] = kf.z;
            Kst[(c4 + 3) * 68 + r] = kf.w;
            float4 vf = *(const float4*)(Vb + (size_t)(kv0 + r) * DIM + c4);
            *(float4*)&Vs[r * 48 + c4] = vf;
        }
        __syncthreads();

        // ---- Phase A: S = Q K^T (this thread: 4 q x 8 kv) ----
        float s[4][8];
#pragma unroll
        for (int i = 0; i < 4; i++)
#pragma unroll
            for (int c = 0; c < 8; c++) s[i][c] = 0.f;

#pragma unroll 4
        for (int d = 0; d < 48; d++) {
            const float4 aq = *(const float4*)&Qst[d * 68 + (ty << 2)];
            const float4 b0 = *(const float4*)&Kst[d * 68 + (tx << 3)];
            const float4 b1 = *(const float4*)&Kst[d * 68 + (tx << 3) + 4];
            float av[4] = {aq.x, aq.y, aq.z, aq.w};
            float bv[8] = {b0.x, b0.y, b0.z, b0.w, b1.x, b1.y, b1.z, b1.w};
#pragma unroll
            for (int i = 0; i < 4; i++)
#pragma unroll
                for (int c = 0; c < 8; c++)
                    s[i][c] += av[i] * bv[c];
        }

        // Online softmax per q row (reduce across the 8 tx lanes)
#pragma unroll
        for (int i = 0; i < 4; i++) {
            float mt = s[i][0];
#pragma unroll
            for (int c = 1; c < 8; c++) mt = fmaxf(mt, s[i][c]);
            mt = fmaxf(mt, __shfl_xor_sync(0xffffffffu, mt, 1));
            mt = fmaxf(mt, __shfl_xor_sync(0xffffffffu, mt, 2));
            mt = fmaxf(mt, __shfl_xor_sync(0xffffffffu, mt, 4));
            float mn = fmaxf(m[i], mt);
            float c0 = __expf(m[i] - mn);
            m[i] = mn;
            float rs = 0.f;
#pragma unroll
            for (int c = 0; c < 8; c++) {
                float p = __expf(s[i][c] - mn);
                s[i][c] = p;
                rs += p;
            }
            rs += __shfl_xor_sync(0xffffffffu, rs, 1);
            rs += __shfl_xor_sync(0xffffffffu, rs, 2);
            rs += __shfl_xor_sync(0xffffffffu, rs, 4);
            l[i] = l[i] * c0 + rs;
            if (tx == 0) corr_s[(ty << 2) + i] = c0;
        }

        // Write P transposed: Pt[kv][q]
#pragma unroll
        for (int c = 0; c < 8; c++) {
            float4 pv = make_float4(s[0][c], s[1][c], s[2][c], s[3][c]);
            *(float4*)&Pt[((tx << 3) + c) * 68 + (ty << 2)] = pv;
        }
        __syncthreads();

        // ---- Phase B: O += P V (this thread: 4 q x 6 d) ----
#pragma unroll
        for (int j = 0; j < 4; j++) {
            float cj = corr_s[(ty << 2) + j];
#pragma unroll
            for (int jj = 0; jj < 6; jj++) o[j][jj] *= cj;
        }
#pragma unroll 4
        for (int k = 0; k < BKV; k++) {
            const float4 a  = *(const float4*)&Pt[k * 68 + (ty << 2)];
            const float2 v0 = *(const float2*)&Vs[k * 48 + tx * 6];
            const float2 v1 = *(const float2*)&Vs[k * 48 + tx * 6 + 2];
            const float2 v2 = *(const float2*)&Vs[k * 48 + tx * 6 + 4];
            float av[4] = {a.x, a.y, a.z, a.w};
            float vv[6] = {v0.x, v0.y, v1.x, v1.y, v2.x, v2.y};
#pragma unroll
            for (int j = 0; j < 4; j++)
#pragma unroll
                for (int jj = 0; jj < 6; jj++)
                    o[j][jj] += av[j] * vv[jj];
        }
    }

    // Epilogue: publish l, divide, store
    __syncthreads();
    if (tx == 0) {
#pragma unroll
        for (int i = 0; i < 4; i++) l_s[(ty << 2) + i] = l[i];
    }
    __syncthreads();

    float* Ob = O + ((size_t)(b * SEQ + q0)) * DIM + h * HD;
#pragma unroll
    for (int j = 0; j < 4; j++) {
        float inv = 1.f / l_s[(ty << 2) + j];
        float* orow = Ob + (size_t)((ty << 2) + j) * DIM + tx * 6;
        float2 w0; w0.x = o[j][0] * inv; w0.y = o[j][1] * inv;
        float2 w1; w1.x = o[j][2] * inv; w1.y = o[j][3] * inv;
        float2 w2; w2.x = o[j][4] * inv; w2.y = o[j][5] * inv;
        *(float2*)(orow)     = w0;
        *(float2*)(orow + 2) = w1;
        *(float2*)(orow + 4) = w2;
    }
}

// ---------------------------------------------------------------------------
// launch
// ---------------------------------------------------------------------------
extern "C" void kernel_launch(void* const* d_in, const int* in_sizes, int n_in,
                              void* d_out, int out_size)
{
    const float* x  = (const float*)d_in[0];
    const float* Wq = (const float*)d_in[1];
    const float* bq = (const float*)d_in[2];
    const float* Wk = (const float*)d_in[3];
    const float* bk = (const float*)d_in[4];
    const float* Wv = (const float*)d_in[5];
    const float* bv = (const float*)d_in[6];
    const float* Wo = (const float*)d_in[7];
    const float* bo = (const float*)d_in[8];
    float* out = (float*)d_out;

    const int M = in_sizes[0] / DIM;   // B*S = 8192
    const int B = M / SEQ;             // 4

    float *qp, *kp, *vp, *aop;
    cudaGetSymbolAddress((void**)&qp,  g_q);
    cudaGetSymbolAddress((void**)&kp,  g_k);
    cudaGetSymbolAddress((void**)&vp,  g_v);
    cudaGetSymbolAddress((void**)&aop, g_ao);

    const int attn_smem = 14080 * 4;   // 56320 bytes
    cudaFuncSetAttribute(flash_attn,
                         cudaFuncAttributeMaxDynamicSharedMemorySize, attn_smem);

    dim3 ggrid(DIM / 128, M / 128);    // (6, 64)
    gemm_nt_bias<<<ggrid, 256>>>(x, Wq, bq, qp, M, DIM, DIM);
    gemm_nt_bias<<<ggrid, 256>>>(x, Wk, bk, kp, M, DIM, DIM);
    gemm_nt_bias<<<ggrid, 256>>>(x, Wv, bv, vp, M, DIM, DIM);

    dim3 agrid(SEQ / BQ, NHEAD, B);    // (32, 16, 4)
    flash_attn<<<agrid, 128, attn_smem>>>(qp, kp, vp, aop);

    gemm_nt_bias<<<ggrid, 256>>>(aop, Wo, bo, out, M, DIM, DIM);
}

// round 3
// speedup vs baseline: 3.0380x; 3.0380x over previous
#include <cuda_runtime.h>
#include <math.h>
#include <stdint.h>

#define DIM 768
#define NHEAD 16
#define HD 48
#define SEQ 2048
#define ATTN_SCALE 0.14433756729740643f  // 1/sqrt(48)

#define BQ 64
#define BKV 64

// ---------------------------------------------------------------------------
// Scratch (device globals: allocation-guard-safe)
// ---------------------------------------------------------------------------
__device__ float g_q[8192 * DIM];
__device__ float g_k[8192 * DIM];
__device__ float g_v[8192 * DIM];
__device__ float g_ao[8192 * DIM];

// ---------------------------------------------------------------------------
// tf32 helpers
// ---------------------------------------------------------------------------
__device__ __forceinline__ uint32_t f2tf(float x) {
    uint32_t r;
    asm("cvt.rna.tf32.f32 %0, %1;" : "=r"(r) : "f"(x));
    return r;
}

// D = A(16x8, row) * B(8x8, col) + D, fp32 accum
__device__ __forceinline__ void mma_tf32(float* c, const uint32_t* a,
                                         uint32_t b0, uint32_t b1) {
    asm volatile(
        "mma.sync.aligned.m16n8k8.row.col.f32.tf32.tf32.f32 "
        "{%0,%1,%2,%3}, {%4,%5,%6,%7}, {%8,%9}, {%0,%1,%2,%3};\n"
        : "+f"(c[0]), "+f"(c[1]), "+f"(c[2]), "+f"(c[3])
        : "r"(a[0]), "r"(a[1]), "r"(a[2]), "r"(a[3]), "r"(b0), "r"(b1));
}

// ---------------------------------------------------------------------------
// GEMM (tf32 tensor core): C[m][n] = sum_k A[m][k]*W[n][k] + bias[n]
// Block tile 128x128, bk=16, 256 threads = 8 warps (2M x 4N),
// warp tile 64x32 = 4x4 m16n8 tiles. Register-prefetch double buffer.
// Shared [row][20] layout: fragment LDS pattern (lane>>2)*20+(lane&3) is
// conflict-free (20*a+b distinct mod 32).
// ---------------------------------------------------------------------------
__global__ __launch_bounds__(256) void gemm_nt_bias_tf32(
    const float* __restrict__ A, const float* __restrict__ W,
    const float* __restrict__ bias, float* __restrict__ C,
    int M, int N, int K)
{
    __shared__ __align__(16) uint32_t As[128 * 20];
    __shared__ __align__(16) uint32_t Ws[128 * 20];

    const int tid  = threadIdx.x;
    const int lane = tid & 31;
    const int warp = tid >> 5;
    const int wm   = (warp >> 2) * 64;   // 0,64
    const int wn   = (warp & 3) * 32;    // 0,32,64,96
    const int g    = lane >> 2;          // 0..7
    const int tq   = lane & 3;           // 0..3

    const int bm = blockIdx.y * 128;
    const int bn = blockIdx.x * 128;

    // staging indices: idx in [0,512): row = idx>>2, c4 = (idx&3)*4
    const int r0 = tid >> 2;             // rows for it=0
    const int c4 = (tid & 3) << 2;

    float acc[4][4][4];
#pragma unroll
    for (int mi = 0; mi < 4; mi++)
#pragma unroll
        for (int ni = 0; ni < 4; ni++)
#pragma unroll
            for (int j = 0; j < 4; j++) acc[mi][ni][j] = 0.f;

    // prologue prefetch (k0 = 0)
    float4 pa0 = *(const float4*)(A + (size_t)(bm + r0) * K + c4);
    float4 pa1 = *(const float4*)(A + (size_t)(bm + r0 + 64) * K + c4);
    float4 pw0 = *(const float4*)(W + (size_t)(bn + r0) * K + c4);
    float4 pw1 = *(const float4*)(W + (size_t)(bn + r0 + 64) * K + c4);

    for (int k0 = 0; k0 < K; k0 += 16) {
        // stage (convert to tf32)
        uint4 ua0 = make_uint4(f2tf(pa0.x), f2tf(pa0.y), f2tf(pa0.z), f2tf(pa0.w));
        uint4 ua1 = make_uint4(f2tf(pa1.x), f2tf(pa1.y), f2tf(pa1.z), f2tf(pa1.w));
        uint4 uw0 = make_uint4(f2tf(pw0.x), f2tf(pw0.y), f2tf(pw0.z), f2tf(pw0.w));
        uint4 uw1 = make_uint4(f2tf(pw1.x), f2tf(pw1.y), f2tf(pw1.z), f2tf(pw1.w));
        *(uint4*)&As[r0 * 20 + c4]        = ua0;
        *(uint4*)&As[(r0 + 64) * 20 + c4] = ua1;
        *(uint4*)&Ws[r0 * 20 + c4]        = uw0;
        *(uint4*)&Ws[(r0 + 64) * 20 + c4] = uw1;
        __syncthreads();

        // prefetch next k-slab
        if (k0 + 16 < K) {
            pa0 = *(const float4*)(A + (size_t)(bm + r0) * K + k0 + 16 + c4);
            pa1 = *(const float4*)(A + (size_t)(bm + r0 + 64) * K + k0 + 16 + c4);
            pw0 = *(const float4*)(W + (size_t)(bn + r0) * K + k0 + 16 + c4);
            pw1 = *(const float4*)(W + (size_t)(bn + r0 + 64) * K + k0 + 16 + c4);
        }

        // compute: two k8 steps
#pragma unroll
        for (int ks = 0; ks < 2; ks++) {
            const int kb = ks * 8;
            uint32_t af[4][4], bf[4][2];
#pragma unroll
            for (int mi = 0; mi < 4; mi++) {
                const int m = wm + mi * 16;
                af[mi][0] = As[(m + g) * 20 + kb + tq];
                af[mi][1] = As[(m + 8 + g) * 20 + kb + tq];
                af[mi][2] = As[(m + g) * 20 + kb + 4 + tq];
                af[mi][3] = As[(m + 8 + g) * 20 + kb + 4 + tq];
            }
#pragma unroll
            for (int ni = 0; ni < 4; ni++) {
                const int n = wn + ni * 8;
                bf[ni][0] = Ws[(n + g) * 20 + kb + tq];
                bf[ni][1] = Ws[(n + g) * 20 + kb + 4 + tq];
            }
#pragma unroll
            for (int mi = 0; mi < 4; mi++)
#pragma unroll
                for (int ni = 0; ni < 4; ni++)
                    mma_tf32(acc[mi][ni], af[mi], bf[ni][0], bf[ni][1]);
        }
        __syncthreads();
    }

    // epilogue: bias + store (fragment: c0 (g,2tq) c1 (g,2tq+1) c2/c3 at g+8)
#pragma unroll
    for (int ni = 0; ni < 4; ni++) {
        const int col = bn + wn + ni * 8 + 2 * tq;
        const float2 bb = *(const float2*)(bias + col);
#pragma unroll
        for (int mi = 0; mi < 4; mi++) {
            const int row = bm + wm + mi * 16 + g;
            float2 v0, v1;
            v0.x = acc[mi][ni][0] + bb.x;
            v0.y = acc[mi][ni][1] + bb.y;
            v1.x = acc[mi][ni][2] + bb.x;
            v1.y = acc[mi][ni][3] + bb.y;
            *(float2*)(C + (size_t)row * N + col)       = v0;
            *(float2*)(C + (size_t)(row + 8) * N + col) = v1;
        }
    }
}

// ---------------------------------------------------------------------------
// Flash attention (tf32 tensor core). Block = 64 q rows of one (b,h),
// 128 threads = 4 warps, warp w owns q rows [w*16, w*16+16).
// kv tiles of 64. S = Q K^T via mma, warp-local online softmax,
// P staged in shared (tf32), O += P V via mma.
//
// Shared (uint32 words, dynamic):
//   Qs[64][52]  [q][d]  scaled tf32      (frag pattern g*20+tq: CF)
//   Ks[64][52]  [kv][d]                  (CF)
//   Vs[64][72]  [kv][d]                  (pattern tq*8+g: CF)
//   Ps[64][68]  [q][kv] tf32             (pattern g*4+tq: CF)
// total (3328+3328+4608+4352)*4 = 62464 bytes
// ---------------------------------------------------------------------------
__global__ __launch_bounds__(128) void flash_attn_tf32(
    const float* __restrict__ Q, const float* __restrict__ K,
    const float* __restrict__ V, float* __restrict__ O)
{
    extern __shared__ uint32_t usm[];
    uint32_t* Qs = usm;              // 64*52
    uint32_t* Ks = usm + 3328;       // 64*52
    uint32_t* Vs = usm + 6656;       // 64*72
    uint32_t* Ps = usm + 11264;      // 64*68

    const int tid  = threadIdx.x;
    const int lane = tid & 31;
    const int w    = tid >> 5;       // warp 0..3
    const int g    = lane >> 2;      // 0..7
    const int tq   = lane & 3;       // 0..3
    const int qw   = w * 16;         // warp's q offset in tile

    const int h  = blockIdx.y;
    const int b  = blockIdx.z;
    const int q0 = blockIdx.x * BQ;

    const float* Qb = Q + ((size_t)(b * SEQ + q0)) * DIM + h * HD;
    const float* Kb = K + (size_t)b * SEQ * DIM + h * HD;
    const float* Vb = V + (size_t)b * SEQ * DIM + h * HD;

    // stage Q (scaled, tf32): 64 rows x 12 float4, 128 threads -> 6 each
#pragma unroll
    for (int i = 0; i < 6; i++) {
        int idx = tid + i * 128;
        int r   = idx / 12;
        int c4  = (idx % 12) << 2;
        float4 f = *(const float4*)(Qb + (size_t)r * DIM + c4);
        uint4 u = make_uint4(f2tf(f.x * ATTN_SCALE), f2tf(f.y * ATTN_SCALE),
                             f2tf(f.z * ATTN_SCALE), f2tf(f.w * ATTN_SCALE));
        *(uint4*)&Qs[r * 52 + c4] = u;
    }
    __syncthreads();

    // persistent Q fragments: 6 k8 steps over d=48
    uint32_t qf[6][4];
#pragma unroll
    for (int kt = 0; kt < 6; kt++) {
        const int kb = kt * 8;
        qf[kt][0] = Qs[(qw + g) * 52 + kb + tq];
        qf[kt][1] = Qs[(qw + 8 + g) * 52 + kb + tq];
        qf[kt][2] = Qs[(qw + g) * 52 + kb + 4 + tq];
        qf[kt][3] = Qs[(qw + 8 + g) * 52 + kb + 4 + tq];
    }

    float oacc[6][4];
#pragma unroll
    for (int ni = 0; ni < 6; ni++)
#pragma unroll
        for (int j = 0; j < 4; j++) oacc[ni][j] = 0.f;
    float mrow[2] = {-1e30f, -1e30f};
    float lrow[2] = {0.f, 0.f};

    for (int kv0 = 0; kv0 < SEQ; kv0 += BKV) {
        __syncthreads();  // Ks/Vs consumers done (prev iter)

        // stage K, V tiles (tf32)
#pragma unroll
        for (int i = 0; i < 6; i++) {
            int idx = tid + i * 128;
            int r   = idx / 12;
            int c4  = (idx % 12) << 2;
            float4 kf = *(const float4*)(Kb + (size_t)(kv0 + r) * DIM + c4);
            float4 vf = *(const float4*)(Vb + (size_t)(kv0 + r) * DIM + c4);
            *(uint4*)&Ks[r * 52 + c4] =
                make_uint4(f2tf(kf.x), f2tf(kf.y), f2tf(kf.z), f2tf(kf.w));
            *(uint4*)&Vs[r * 72 + c4] =
                make_uint4(f2tf(vf.x), f2tf(vf.y), f2tf(vf.z), f2tf(vf.w));
        }
        __syncthreads();

        // ---- S = Q K^T : warp computes m16 x n64 (8 n-tiles) ----
        float sacc[8][4];
#pragma unroll
        for (int ni = 0; ni < 8; ni++)
#pragma unroll
            for (int j = 0; j < 4; j++) sacc[ni][j] = 0.f;

#pragma unroll
        for (int kt = 0; kt < 6; kt++) {
            const int kb = kt * 8;
#pragma unroll
            for (int ni = 0; ni < 8; ni++) {
                const int n = ni * 8;
                uint32_t b0 = Ks[(n + g) * 52 + kb + tq];
                uint32_t b1 = Ks[(n + g) * 52 + kb + 4 + tq];
                mma_tf32(sacc[ni], qf[kt], b0, b1);
            }
        }

        // ---- online softmax (rows g and g+8 of warp tile) ----
        float mx0 = -1e30f, mx1 = -1e30f;
#pragma unroll
        for (int ni = 0; ni < 8; ni++) {
            mx0 = fmaxf(mx0, fmaxf(sacc[ni][0], sacc[ni][1]));
            mx1 = fmaxf(mx1, fmaxf(sacc[ni][2], sacc[ni][3]));
        }
        mx0 = fmaxf(mx0, __shfl_xor_sync(0xffffffffu, mx0, 1));
        mx0 = fmaxf(mx0, __shfl_xor_sync(0xffffffffu, mx0, 2));
        mx1 = fmaxf(mx1, __shfl_xor_sync(0xffffffffu, mx1, 1));
        mx1 = fmaxf(mx1, __shfl_xor_sync(0xffffffffu, mx1, 2));

        const float mn0 = fmaxf(mrow[0], mx0);
        const float mn1 = fmaxf(mrow[1], mx1);
        const float cr0 = __expf(mrow[0] - mn0);
        const float cr1 = __expf(mrow[1] - mn1);
        mrow[0] = mn0; mrow[1] = mn1;

        float rs0 = 0.f, rs1 = 0.f;
#pragma unroll
        for (int ni = 0; ni < 8; ni++) {
            sacc[ni][0] = __expf(sacc[ni][0] - mn0);
            sacc[ni][1] = __expf(sacc[ni][1] - mn0);
            sacc[ni][2] = __expf(sacc[ni][2] - mn1);
            sacc[ni][3] = __expf(sacc[ni][3] - mn1);
            rs0 += sacc[ni][0] + sacc[ni][1];
            rs1 += sacc[ni][2] + sacc[ni][3];
        }
        rs0 += __shfl_xor_sync(0xffffffffu, rs0, 1);
        rs0 += __shfl_xor_sync(0xffffffffu, rs0, 2);
        rs1 += __shfl_xor_sync(0xffffffffu, rs1, 1);
        rs1 += __shfl_xor_sync(0xffffffffu, rs1, 2);
        lrow[0] = lrow[0] * cr0 + rs0;
        lrow[1] = lrow[1] * cr1 + rs1;

        // rescale O accumulators
#pragma unroll
        for (int ni = 0; ni < 6; ni++) {
            oacc[ni][0] *= cr0; oacc[ni][1] *= cr0;
            oacc[ni][2] *= cr1; oacc[ni][3] *= cr1;
        }

        // ---- write P (tf32) to this warp's Ps slice ----
#pragma unroll
        for (int ni = 0; ni < 8; ni++) {
            const int col = ni * 8 + 2 * tq;
            uint2 p0 = make_uint2(f2tf(sacc[ni][0]), f2tf(sacc[ni][1]));
            uint2 p1 = make_uint2(f2tf(sacc[ni][2]), f2tf(sacc[ni][3]));
            *(uint2*)&Ps[(qw + g) * 68 + col]     = p0;
            *(uint2*)&Ps[(qw + 8 + g) * 68 + col] = p1;
        }
        __syncwarp();

        // ---- O += P V : A = P (16 x 64, 8 k8), B = V (6 n-tiles of d) ----
#pragma unroll
        for (int kt = 0; kt < 8; kt++) {
            const int kb = kt * 8;
            uint32_t af[4];
            af[0] = Ps[(qw + g) * 68 + kb + tq];
            af[1] = Ps[(qw + 8 + g) * 68 + kb + tq];
            af[2] = Ps[(qw + g) * 68 + kb + 4 + tq];
            af[3] = Ps[(qw + 8 + g) * 68 + kb + 4 + tq];
#pragma unroll
            for (int ni = 0; ni < 6; ni++) {
                const int n = ni * 8;
                uint32_t b0 = Vs[(kb + tq) * 72 + n + g];
                uint32_t b1 = Vs[(kb + 4 + tq) * 72 + n + g];
                mma_tf32(oacc[ni], af, b0, b1);
            }
        }
    }

    // ---- epilogue ----
    const float inv0 = 1.f / lrow[0];
    const float inv1 = 1.f / lrow[1];
    float* Ob = O + ((size_t)(b * SEQ + q0 + qw)) * DIM + h * HD;
#pragma unroll
    for (int ni = 0; ni < 6; ni++) {
        const int col = ni * 8 + 2 * tq;
        float2 v0, v1;
        v0.x = oacc[ni][0] * inv0; v0.y = oacc[ni][1] * inv0;
        v1.x = oacc[ni][2] * inv1; v1.y = oacc[ni][3] * inv1;
        *(float2*)(Ob + (size_t)g * DIM + col)       = v0;
        *(float2*)(Ob + (size_t)(g + 8) * DIM + col) = v1;
    }
}

// ---------------------------------------------------------------------------
// launch
// ---------------------------------------------------------------------------
extern "C" void kernel_launch(void* const* d_in, const int* in_sizes, int n_in,
                              void* d_out, int out_size)
{
    const float* x  = (const float*)d_in[0];
    const float* Wq = (const float*)d_in[1];
    const float* bq = (const float*)d_in[2];
    const float* Wk = (const float*)d_in[3];
    const float* bk = (const float*)d_in[4];
    const float* Wv = (const float*)d_in[5];
    const float* bv = (const float*)d_in[6];
    const float* Wo = (const float*)d_in[7];
    const float* bo = (const float*)d_in[8];
    float* out = (float*)d_out;

    const int M = in_sizes[0] / DIM;   // B*S = 8192
    const int B = M / SEQ;             // 4

    float *qp, *kp, *vp, *aop;
    cudaGetSymbolAddress((void**)&qp,  g_q);
    cudaGetSymbolAddress((void**)&kp,  g_k);
    cudaGetSymbolAddress((void**)&vp,  g_v);
    cudaGetSymbolAddress((void**)&aop, g_ao);

    const int attn_smem = 15616 * 4;   // 62464 bytes
    cudaFuncSetAttribute(flash_attn_tf32,
                         cudaFuncAttributeMaxDynamicSharedMemorySize, attn_smem);

    dim3 ggrid(DIM / 128, M / 128);    // (6, 64)
    gemm_nt_bias_tf32<<<ggrid, 256>>>(x, Wq, bq, qp, M, DIM, DIM);
    gemm_nt_bias_tf32<<<ggrid, 256>>>(x, Wk, bk, kp, M, DIM, DIM);
    gemm_nt_bias_tf32<<<ggrid, 256>>>(x, Wv, bv, vp, M, DIM, DIM);

    dim3 agrid(SEQ / BQ, NHEAD, B);    // (32, 16, 4)
    flash_attn_tf32<<<agrid, 128, attn_smem>>>(qp, kp, vp, aop);

    gemm_nt_bias_tf32<<<ggrid, 256>>>(aop, Wo, bo, out, M, DIM, DIM);
}

// round 4
// speedup vs baseline: 3.3482x; 1.1021x over previous
#include <cuda_runtime.h>
#include <math.h>
#include <stdint.h>

#define DIM 768
#define NHEAD 16
#define HD 48
#define SEQ 2048
#define ATTN_SCALE 0.14433756729740643f  // 1/sqrt(48)

#define BQ 128
#define BKV 64

// ---------------------------------------------------------------------------
// Scratch (device globals: allocation-guard-safe)
// ---------------------------------------------------------------------------
__device__ float g_q[8192 * DIM];
__device__ float g_k[8192 * DIM];
__device__ float g_v[8192 * DIM];
__device__ float g_ao[8192 * DIM];

// ---------------------------------------------------------------------------
// tf32 helpers
// ---------------------------------------------------------------------------
__device__ __forceinline__ uint32_t f2tf(float x) {
    uint32_t r;
    asm("cvt.rna.tf32.f32 %0, %1;" : "=r"(r) : "f"(x));
    return r;
}

// D = A(16x8, row) * B(8x8, col) + D, fp32 accum
__device__ __forceinline__ void mma_tf32(float* c, const uint32_t* a,
                                         uint32_t b0, uint32_t b1) {
    asm volatile(
        "mma.sync.aligned.m16n8k8.row.col.f32.tf32.tf32.f32 "
        "{%0,%1,%2,%3}, {%4,%5,%6,%7}, {%8,%9}, {%0,%1,%2,%3};\n"
        : "+f"(c[0]), "+f"(c[1]), "+f"(c[2]), "+f"(c[3])
        : "r"(a[0]), "r"(a[1]), "r"(a[2]), "r"(a[3]), "r"(b0), "r"(b1));
}

// ---------------------------------------------------------------------------
// GEMM (tf32 tensor core): C[m][n] = sum_k A[m][k]*W[n][k] + bias[n]
// Block tile 128x128, bk=16, 256 threads = 8 warps (2M x 4N),
// warp tile 64x32 = 4x4 m16n8 tiles. Register-prefetch double buffer.
// ---------------------------------------------------------------------------
__global__ __launch_bounds__(256) void gemm_nt_bias_tf32(
    const float* __restrict__ A, const float* __restrict__ W,
    const float* __restrict__ bias, float* __restrict__ C,
    int M, int N, int K)
{
    __shared__ __align__(16) uint32_t As[128 * 20];
    __shared__ __align__(16) uint32_t Ws[128 * 20];

    const int tid  = threadIdx.x;
    const int lane = tid & 31;
    const int warp = tid >> 5;
    const int wm   = (warp >> 2) * 64;
    const int wn   = (warp & 3) * 32;
    const int g    = lane >> 2;
    const int tq   = lane & 3;

    const int bm = blockIdx.y * 128;
    const int bn = blockIdx.x * 128;

    const int r0 = tid >> 2;
    const int c4 = (tid & 3) << 2;

    float acc[4][4][4];
#pragma unroll
    for (int mi = 0; mi < 4; mi++)
#pragma unroll
        for (int ni = 0; ni < 4; ni++)
#pragma unroll
            for (int j = 0; j < 4; j++) acc[mi][ni][j] = 0.f;

    float4 pa0 = *(const float4*)(A + (size_t)(bm + r0) * K + c4);
    float4 pa1 = *(const float4*)(A + (size_t)(bm + r0 + 64) * K + c4);
    float4 pw0 = *(const float4*)(W + (size_t)(bn + r0) * K + c4);
    float4 pw1 = *(const float4*)(W + (size_t)(bn + r0 + 64) * K + c4);

    for (int k0 = 0; k0 < K; k0 += 16) {
        uint4 ua0 = make_uint4(f2tf(pa0.x), f2tf(pa0.y), f2tf(pa0.z), f2tf(pa0.w));
        uint4 ua1 = make_uint4(f2tf(pa1.x), f2tf(pa1.y), f2tf(pa1.z), f2tf(pa1.w));
        uint4 uw0 = make_uint4(f2tf(pw0.x), f2tf(pw0.y), f2tf(pw0.z), f2tf(pw0.w));
        uint4 uw1 = make_uint4(f2tf(pw1.x), f2tf(pw1.y), f2tf(pw1.z), f2tf(pw1.w));
        *(uint4*)&As[r0 * 20 + c4]        = ua0;
        *(uint4*)&As[(r0 + 64) * 20 + c4] = ua1;
        *(uint4*)&Ws[r0 * 20 + c4]        = uw0;
        *(uint4*)&Ws[(r0 + 64) * 20 + c4] = uw1;
        __syncthreads();

        if (k0 + 16 < K) {
            pa0 = *(const float4*)(A + (size_t)(bm + r0) * K + k0 + 16 + c4);
            pa1 = *(const float4*)(A + (size_t)(bm + r0 + 64) * K + k0 + 16 + c4);
            pw0 = *(const float4*)(W + (size_t)(bn + r0) * K + k0 + 16 + c4);
            pw1 = *(const float4*)(W + (size_t)(bn + r0 + 64) * K + k0 + 16 + c4);
        }

#pragma unroll
        for (int ks = 0; ks < 2; ks++) {
            const int kb = ks * 8;
            uint32_t af[4][4], bf[4][2];
#pragma unroll
            for (int mi = 0; mi < 4; mi++) {
                const int m = wm + mi * 16;
                af[mi][0] = As[(m + g) * 20 + kb + tq];
                af[mi][1] = As[(m + 8 + g) * 20 + kb + tq];
                af[mi][2] = As[(m + g) * 20 + kb + 4 + tq];
                af[mi][3] = As[(m + 8 + g) * 20 + kb + 4 + tq];
            }
#pragma unroll
            for (int ni = 0; ni < 4; ni++) {
                const int n = wn + ni * 8;
                bf[ni][0] = Ws[(n + g) * 20 + kb + tq];
                bf[ni][1] = Ws[(n + g) * 20 + kb + 4 + tq];
            }
#pragma unroll
            for (int mi = 0; mi < 4; mi++)
#pragma unroll
                for (int ni = 0; ni < 4; ni++)
                    mma_tf32(acc[mi][ni], af[mi], bf[ni][0], bf[ni][1]);
        }
        __syncthreads();
    }

#pragma unroll
    for (int ni = 0; ni < 4; ni++) {
        const int col = bn + wn + ni * 8 + 2 * tq;
        const float2 bb = *(const float2*)(bias + col);
#pragma unroll
        for (int mi = 0; mi < 4; mi++) {
            const int row = bm + wm + mi * 16 + g;
            float2 v0, v1;
            v0.x = acc[mi][ni][0] + bb.x;
            v0.y = acc[mi][ni][1] + bb.y;
            v1.x = acc[mi][ni][2] + bb.x;
            v1.y = acc[mi][ni][3] + bb.y;
            *(float2*)(C + (size_t)row * N + col)       = v0;
            *(float2*)(C + (size_t)(row + 8) * N + col) = v1;
        }
    }
}

// ---------------------------------------------------------------------------
// Flash attention v3 (tf32 mma). Block = 128 q rows of one (b,h), 128 threads
// = 4 warps; warp w owns q rows [32w,32w+32) = two m16 subtiles (sequential,
// so sacc is transient). kv tiles of 64.
//
// Shared (uint32 words, dynamic):
//   Ps[128][72]  [q][kv] tf32   ofs 0     (9216)   -- overlapped with
//   Qs[128][52]  [q][d]  (staging only, dead after qf regs loaded)
//   Ks[64][52]   [kv][d]        ofs 9216  (3328)
//   Vs[64][72]   [kv][d]        ofs 12544 (4608)
// total 17152 words = 68608 bytes
// All fragment access patterns bank-conflict-free (strides 52 / 72).
// ---------------------------------------------------------------------------
__global__ __launch_bounds__(128) void flash_attn_tf32_v3(
    const float* __restrict__ Q, const float* __restrict__ K,
    const float* __restrict__ V, float* __restrict__ O)
{
    extern __shared__ uint32_t usm[];
    uint32_t* Ps = usm;              // [128][72]
    uint32_t* Qs = usm;              // [128][52] (staging alias)
    uint32_t* Ks = usm + 9216;       // [64][52]
    uint32_t* Vs = usm + 12544;      // [64][72]

    const int tid  = threadIdx.x;
    const int lane = tid & 31;
    const int w    = tid >> 5;       // warp 0..3
    const int g    = lane >> 2;      // 0..7
    const int tq   = lane & 3;       // 0..3
    const int qw   = w * 32;         // warp's q offset in CTA tile

    const int h  = blockIdx.y;
    const int b  = blockIdx.z;
    const int q0 = blockIdx.x * BQ;

    const float* Qb = Q + ((size_t)(b * SEQ + q0)) * DIM + h * HD;
    const float* Kb = K + (size_t)b * SEQ * DIM + h * HD;
    const float* Vb = V + (size_t)b * SEQ * DIM + h * HD;

    // ---- stage Q (scaled, tf32): 128 rows x 12 float4 ----
#pragma unroll
    for (int i = 0; i < 12; i++) {
        int idx = tid + i * 128;
        int r   = idx / 12;
        int c4  = (idx % 12) << 2;
        float4 f = *(const float4*)(Qb + (size_t)r * DIM + c4);
        uint4 u = make_uint4(f2tf(f.x * ATTN_SCALE), f2tf(f.y * ATTN_SCALE),
                             f2tf(f.z * ATTN_SCALE), f2tf(f.w * ATTN_SCALE));
        *(uint4*)&Qs[r * 52 + c4] = u;
    }
    __syncthreads();

    // persistent Q fragments: 2 subtiles x 6 k8 steps
    uint32_t qf[2][6][4];
#pragma unroll
    for (int sub = 0; sub < 2; sub++) {
        const int qb = qw + sub * 16;
#pragma unroll
        for (int kt = 0; kt < 6; kt++) {
            const int kb = kt * 8;
            qf[sub][kt][0] = Qs[(qb + g) * 52 + kb + tq];
            qf[sub][kt][1] = Qs[(qb + 8 + g) * 52 + kb + tq];
            qf[sub][kt][2] = Qs[(qb + g) * 52 + kb + 4 + tq];
            qf[sub][kt][3] = Qs[(qb + 8 + g) * 52 + kb + 4 + tq];
        }
    }

    float oacc[2][6][4];
#pragma unroll
    for (int sub = 0; sub < 2; sub++)
#pragma unroll
        for (int ni = 0; ni < 6; ni++)
#pragma unroll
            for (int j = 0; j < 4; j++) oacc[sub][ni][j] = 0.f;
    float mrow[2][2] = {{-1e30f, -1e30f}, {-1e30f, -1e30f}};
    float lrow[2][2] = {{0.f, 0.f}, {0.f, 0.f}};

    for (int kv0 = 0; kv0 < SEQ; kv0 += BKV) {
        __syncthreads();  // all consumers of Ks/Vs (and Qs on iter 0) done

        // ---- stage K, V tiles (tf32): 64 rows x 12 float4 each ----
#pragma unroll
        for (int i = 0; i < 6; i++) {
            int idx = tid + i * 128;
            int r   = idx / 12;
            int c4  = (idx % 12) << 2;
            float4 kf = *(const float4*)(Kb + (size_t)(kv0 + r) * DIM + c4);
            float4 vf = *(const float4*)(Vb + (size_t)(kv0 + r) * DIM + c4);
            *(uint4*)&Ks[r * 52 + c4] =
                make_uint4(f2tf(kf.x), f2tf(kf.y), f2tf(kf.z), f2tf(kf.w));
            *(uint4*)&Vs[r * 72 + c4] =
                make_uint4(f2tf(vf.x), f2tf(vf.y), f2tf(vf.z), f2tf(vf.w));
        }
        __syncthreads();

        // ---- per subtile: S = Q K^T, softmax, write P ----
#pragma unroll
        for (int sub = 0; sub < 2; sub++) {
            const int qb = qw + sub * 16;

            float sacc[8][4];
#pragma unroll
            for (int ni = 0; ni < 8; ni++)
#pragma unroll
                for (int j = 0; j < 4; j++) sacc[ni][j] = 0.f;

#pragma unroll
            for (int kt = 0; kt < 6; kt++) {
                const int kb = kt * 8;
#pragma unroll
                for (int ni = 0; ni < 8; ni++) {
                    const int n = ni * 8;
                    uint32_t b0 = Ks[(n + g) * 52 + kb + tq];
                    uint32_t b1 = Ks[(n + g) * 52 + kb + 4 + tq];
                    mma_tf32(sacc[ni], qf[sub][kt], b0, b1);
                }
            }

            // online softmax (rows g, g+8 of subtile)
            float mx0 = -1e30f, mx1 = -1e30f;
#pragma unroll
            for (int ni = 0; ni < 8; ni++) {
                mx0 = fmaxf(mx0, fmaxf(sacc[ni][0], sacc[ni][1]));
                mx1 = fmaxf(mx1, fmaxf(sacc[ni][2], sacc[ni][3]));
            }
            mx0 = fmaxf(mx0, __shfl_xor_sync(0xffffffffu, mx0, 1));
            mx0 = fmaxf(mx0, __shfl_xor_sync(0xffffffffu, mx0, 2));
            mx1 = fmaxf(mx1, __shfl_xor_sync(0xffffffffu, mx1, 1));
            mx1 = fmaxf(mx1, __shfl_xor_sync(0xffffffffu, mx1, 2));

            const float mn0 = fmaxf(mrow[sub][0], mx0);
            const float mn1 = fmaxf(mrow[sub][1], mx1);
            const float cr0 = __expf(mrow[sub][0] - mn0);
            const float cr1 = __expf(mrow[sub][1] - mn1);
            mrow[sub][0] = mn0; mrow[sub][1] = mn1;

            float rs0 = 0.f, rs1 = 0.f;
#pragma unroll
            for (int ni = 0; ni < 8; ni++) {
                sacc[ni][0] = __expf(sacc[ni][0] - mn0);
                sacc[ni][1] = __expf(sacc[ni][1] - mn0);
                sacc[ni][2] = __expf(sacc[ni][2] - mn1);
                sacc[ni][3] = __expf(sacc[ni][3] - mn1);
                rs0 += sacc[ni][0] + sacc[ni][1];
                rs1 += sacc[ni][2] + sacc[ni][3];
            }
            rs0 += __shfl_xor_sync(0xffffffffu, rs0, 1);
            rs0 += __shfl_xor_sync(0xffffffffu, rs0, 2);
            rs1 += __shfl_xor_sync(0xffffffffu, rs1, 1);
            rs1 += __shfl_xor_sync(0xffffffffu, rs1, 2);
            lrow[sub][0] = lrow[sub][0] * cr0 + rs0;
            lrow[sub][1] = lrow[sub][1] * cr1 + rs1;

#pragma unroll
            for (int ni = 0; ni < 6; ni++) {
                oacc[sub][ni][0] *= cr0; oacc[sub][ni][1] *= cr0;
                oacc[sub][ni][2] *= cr1; oacc[sub][ni][3] *= cr1;
            }

            // write P (tf32) to this warp's rows (stride 72: conflict-free)
#pragma unroll
            for (int ni = 0; ni < 8; ni++) {
                const int col = ni * 8 + 2 * tq;
                uint2 p0 = make_uint2(f2tf(sacc[ni][0]), f2tf(sacc[ni][1]));
                uint2 p1 = make_uint2(f2tf(sacc[ni][2]), f2tf(sacc[ni][3]));
                *(uint2*)&Ps[(qb + g) * 72 + col]     = p0;
                *(uint2*)&Ps[(qb + 8 + g) * 72 + col] = p1;
            }
        }
        __syncwarp();  // P is warp-local: own warp wrote / reads its 32 rows

        // ---- O += P V ----
#pragma unroll
        for (int sub = 0; sub < 2; sub++) {
            const int qb = qw + sub * 16;
#pragma unroll
            for (int kt = 0; kt < 8; kt++) {
                const int kb = kt * 8;
                uint32_t af[4];
                af[0] = Ps[(qb + g) * 72 + kb + tq];
                af[1] = Ps[(qb + 8 + g) * 72 + kb + tq];
                af[2] = Ps[(qb + g) * 72 + kb + 4 + tq];
                af[3] = Ps[(qb + 8 + g) * 72 + kb + 4 + tq];
#pragma unroll
                for (int ni = 0; ni < 6; ni++) {
                    const int n = ni * 8;
                    uint32_t b0 = Vs[(kb + tq) * 72 + n + g];
                    uint32_t b1 = Vs[(kb + 4 + tq) * 72 + n + g];
                    mma_tf32(oacc[sub][ni], af, b0, b1);
                }
            }
        }
    }

    // ---- epilogue ----
#pragma unroll
    for (int sub = 0; sub < 2; sub++) {
        const float inv0 = 1.f / lrow[sub][0];
        const float inv1 = 1.f / lrow[sub][1];
        float* Ob = O + ((size_t)(b * SEQ + q0 + qw + sub * 16)) * DIM + h * HD;
#pragma unroll
        for (int ni = 0; ni < 6; ni++) {
            const int col = ni * 8 + 2 * tq;
            float2 v0, v1;
            v0.x = oacc[sub][ni][0] * inv0; v0.y = oacc[sub][ni][1] * inv0;
            v1.x = oacc[sub][ni][2] * inv1; v1.y = oacc[sub][ni][3] * inv1;
            *(float2*)(Ob + (size_t)g * DIM + col)       = v0;
            *(float2*)(Ob + (size_t)(g + 8) * DIM + col) = v1;
        }
    }
}

// ---------------------------------------------------------------------------
// launch
// ---------------------------------------------------------------------------
extern "C" void kernel_launch(void* const* d_in, const int* in_sizes, int n_in,
                              void* d_out, int out_size)
{
    const float* x  = (const float*)d_in[0];
    const float* Wq = (const float*)d_in[1];
    const float* bq = (const float*)d_in[2];
    const float* Wk = (const float*)d_in[3];
    const float* bk = (const float*)d_in[4];
    const float* Wv = (const float*)d_in[5];
    const float* bv = (const float*)d_in[6];
    const float* Wo = (const float*)d_in[7];
    const float* bo = (const float*)d_in[8];
    float* out = (float*)d_out;

    const int M = in_sizes[0] / DIM;   // B*S = 8192
    const int B = M / SEQ;             // 4

    float *qp, *kp, *vp, *aop;
    cudaGetSymbolAddress((void**)&qp,  g_q);
    cudaGetSymbolAddress((void**)&kp,  g_k);
    cudaGetSymbolAddress((void**)&vp,  g_v);
    cudaGetSymbolAddress((void**)&aop, g_ao);

    const int attn_smem = 17152 * 4;   // 68608 bytes
    cudaFuncSetAttribute(flash_attn_tf32_v3,
                         cudaFuncAttributeMaxDynamicSharedMemorySize, attn_smem);

    dim3 ggrid(DIM / 128, M / 128);    // (6, 64)
    gemm_nt_bias_tf32<<<ggrid, 256>>>(x, Wq, bq, qp, M, DIM, DIM);
    gemm_nt_bias_tf32<<<ggrid, 256>>>(x, Wk, bk, kp, M, DIM, DIM);
    gemm_nt_bias_tf32<<<ggrid, 256>>>(x, Wv, bv, vp, M, DIM, DIM);

    dim3 agrid(SEQ / BQ, NHEAD, B);    // (16, 16, 4)
    flash_attn_tf32_v3<<<agrid, 128, attn_smem>>>(qp, kp, vp, aop);

    gemm_nt_bias_tf32<<<ggrid, 256>>>(aop, Wo, bo, out, M, DIM, DIM);
}